// round 7
// baseline (speedup 1.0000x reference)
#include <cuda_runtime.h>
#include <cstdint>

#define B_ 8
#define N_ 10000
#define C_ 80
#define K_ 8
#define THR 0.5f
#define T2  0.99f            // collection threshold: ~100 candidates/class
#define FNEGMAX -3.402823466e38f
#define NMS_NEG -1e9f
#define CAP 256

typedef unsigned long long u64;

// Scratch (allocation-free rule: __device__ globals; zero-initialized, and
// every launch restores counters to zero => graph-replay deterministic)
__device__ u64    g_cand[B_ * C_ * CAP];
__device__ int    g_ccnt[B_ * C_];
__device__ float  g_sel_score[B_ * C_ * K_];
__device__ float4 g_sel_box  [B_ * C_ * K_];
__device__ int    g_sel_valid[B_ * C_ * K_];
__device__ int    g_done_count;

// key = (score_bits, N-n): max-key == (max score, lowest n). Valid scores are
// > 0.5 (positive floats: uint order == float order); 0 = empty sentinel.
__device__ __forceinline__ u64 mkey(float v, int n) {
    return (((u64)__float_as_uint(v)) << 32) | (unsigned)(N_ - n);
}

__device__ __forceinline__ bool sup_iou(float4 a, float4 q) {
    float ih = fmaxf(fminf(a.z, q.z) - fmaxf(a.x, q.x), 0.0f);
    float iw = fmaxf(fminf(a.w, q.w) - fmaxf(a.y, q.y), 0.0f);
    float inter = ih * iw;
    float uni = (a.z - a.x) * (a.w - a.y) + (q.z - q.x) * (q.w - q.y) - inter;
    return inter / fmaxf(uni, 1e-9f) > 0.5f;
}

// ---------------------------------------------------------------------------
// Phase 1: coalesced stream over scores [B,N,C]; every value > T2 appends a
// key to its class list. grid (196, B), 256 thr, 4 float4 per thread.
// ---------------------------------------------------------------------------
__global__ __launch_bounds__(256) void p1_collect(const float* __restrict__ scores)
{
    const int b = blockIdx.y;
    const int base = b * C_;
    const float4* sp = reinterpret_cast<const float4*>(scores) + (size_t)b * 200000;

    #pragma unroll
    for (int k = 0; k < 4; k++) {
        int idx4 = blockIdx.x * 1024 + k * 256 + threadIdx.x;
        if (idx4 < 200000) {                       // N*C/4
            float4 v = __ldg(sp + idx4);
            int n  = idx4 / 20;                    // 20 float4 per 80-col row
            int c0 = (idx4 - n * 20) * 4;
            if (v.x > T2) { int p = atomicAdd(&g_ccnt[base+c0  ], 1); if (p < CAP) g_cand[(base+c0  )*CAP+p] = mkey(v.x, n); }
            if (v.y > T2) { int p = atomicAdd(&g_ccnt[base+c0+1], 1); if (p < CAP) g_cand[(base+c0+1)*CAP+p] = mkey(v.y, n); }
            if (v.z > T2) { int p = atomicAdd(&g_ccnt[base+c0+2], 1); if (p < CAP) g_cand[(base+c0+2)*CAP+p] = mkey(v.z, n); }
            if (v.w > T2) { int p = atomicAdd(&g_ccnt[base+c0+3], 1); if (p < CAP) g_cand[(base+c0+3)*CAP+p] = mkey(v.w, n); }
        }
    }
}

// ---------------------------------------------------------------------------
// Phase 2: one 128-thread block per (b,c). Warp 0: keys in registers (8/lane),
// pop-by-max greedy NMS with batched box prefetch + warp-parallel IoU.
// Exact fallback (raw-score rescan) if candidates can't fill K or overflow.
// Last block (atomic ticket) runs the fused per-batch top-8.
// Output (f32): boxes[8][8][4] | scores[8][8] | classes[8][8] | valid[8]
// ---------------------------------------------------------------------------
__global__ __launch_bounds__(128) void p2_nms(
    const float* __restrict__ boxes, const float* __restrict__ scores,
    float* __restrict__ out)
{
    __shared__ u64    buf[2560];          // 20KB: aliased as topk float buffer
    __shared__ float4 selbox[K_];
    __shared__ float  selsc[K_];
    __shared__ int    sel_n[K_];
    __shared__ int    sh_nsel, sh_ticket, sh_cnt;

    const int tid  = threadIdx.x;
    const int lane = tid & 31;
    const int blk  = blockIdx.x;
    const int b    = blk / C_;
    const int c    = blk % C_;

    if (tid == 0) { sh_cnt = g_ccnt[blk]; g_ccnt[blk] = 0; }   // self-clean
    __syncthreads();
    const int  cnt  = sh_cnt;
    const bool over = cnt > CAP;
    const int  m    = over ? 0 : cnt;     // overflow: set unusable -> fallback

    if (tid < 32) {
        const float4* bxp = reinterpret_cast<const float4*>(boxes) + (size_t)b * N_;

        u64 k[8];
        #pragma unroll
        for (int j = 0; j < 8; j++) {
            int idx = lane + (j << 5);
            k[j] = (idx < m) ? __ldg(&g_cand[blk * CAP + idx]) : 0ULL;
        }

        int  nsel = 0;
        bool exhausted = (m == 0);
        while (nsel < K_ && !exhausted) {
            float4 myb = make_float4(0.f, 0.f, 0.f, 0.f);
            float  mysc = 0.f;
            int    myn  = 0;
            int    npop = 0;
            for (int p = 0; p < 8; p++) {
                u64 g = k[0];
                #pragma unroll
                for (int j = 1; j < 8; j++) if (k[j] > g) g = k[j];
                #pragma unroll
                for (int off = 16; off > 0; off >>= 1) {
                    u64 og = __shfl_down_sync(0xffffffffu, g, off);
                    if (og > g) g = og;
                }
                g = __shfl_sync(0xffffffffu, g, 0);
                if ((unsigned)(g >> 32) == 0u) { exhausted = true; break; }
                if (lane == p) {
                    mysc = __uint_as_float((unsigned)(g >> 32));
                    myn  = N_ - (int)(g & 0xffffffffu);
                    myb  = __ldg(bxp + myn);       // prefetch, overlaps pops
                }
                #pragma unroll
                for (int j = 0; j < 8; j++) if (k[j] == g) k[j] = 0;  // kill
                npop++;
            }

            for (int q = 0; q < npop && nsel < K_; q++) {
                float4 bb;
                bb.x = __shfl_sync(0xffffffffu, myb.x, q);
                bb.y = __shfl_sync(0xffffffffu, myb.y, q);
                bb.z = __shfl_sync(0xffffffffu, myb.z, q);
                bb.w = __shfl_sync(0xffffffffu, myb.w, q);
                float scq = __shfl_sync(0xffffffffu, mysc, q);
                int   nq  = __shfl_sync(0xffffffffu, myn, q);
                bool sup = (lane < nsel) ? sup_iou(bb, selbox[lane]) : false;
                if (!__ballot_sync(0xffffffffu, sup)) {
                    if (lane == 0) {
                        selbox[nsel] = bb; selsc[nsel] = scq; sel_n[nsel] = nq;
                    }
                    nsel++;
                    __syncwarp();
                }
            }
        }

        // ---- exact fallback (probability ~0 on this data) ----
        if (nsel < K_) {
            const float* scp = scores + (size_t)b * N_ * C_ + c;
            while (nsel < K_) {
                u64 best = 0;
                for (int n = lane; n < N_; n += 32) {
                    float v = __ldg(scp + (size_t)n * C_);
                    if (v > THR) {
                        bool excl = false;
                        for (int j = 0; j < nsel; j++) if (sel_n[j] == n) excl = true;
                        if (!excl) {
                            float4 bb = __ldg(bxp + n);
                            for (int j = 0; j < nsel; j++)
                                if (sup_iou(bb, selbox[j])) { excl = true; break; }
                        }
                        if (!excl) { u64 kk = mkey(v, n); if (kk > best) best = kk; }
                    }
                }
                #pragma unroll
                for (int off = 16; off > 0; off >>= 1) {
                    u64 ob = __shfl_down_sync(0xffffffffu, best, off);
                    if (ob > best) best = ob;
                }
                best = __shfl_sync(0xffffffffu, best, 0);
                if ((unsigned)(best >> 32) == 0u) break;
                int nn = N_ - (int)(best & 0xffffffffu);
                if (lane == 0) {
                    selbox[nsel] = __ldg(bxp + nn);
                    selsc[nsel]  = __uint_as_float((unsigned)(best >> 32));
                    sel_n[nsel]  = nn;
                }
                nsel++;
                __syncwarp();
            }
        }
        if (lane == 0) sh_nsel = nsel;
    }
    __syncthreads();

    if (tid < K_) {
        int o = blk * K_ + tid;
        int v = (tid < sh_nsel);
        g_sel_valid[o] = v;
        g_sel_score[o] = v ? selsc[tid] : NMS_NEG;
        float4 z = make_float4(0.f, 0.f, 0.f, 0.f);
        g_sel_box[o] = v ? selbox[tid] : z;
    }
    __threadfence();
    __syncthreads();
    if (tid == 0) sh_ticket = atomicAdd(&g_done_count, 1);
    __syncthreads();
    if (sh_ticket != B_ * C_ - 1) return;
    __threadfence();

    // ---- fused final top-8 (last block only): 4 warps x 2 batches ----
    float* sc = reinterpret_cast<float*>(buf);
    const int warp = tid >> 5;
    for (int wb = warp; wb < B_; wb += 4) {
        const int base = wb * C_ * K_;
        for (int j2 = lane; j2 < C_ * K_; j2 += 32)
            sc[wb * 640 + j2] = g_sel_score[base + j2];
        __syncwarp();

        int vcnt = 0;
        for (int k = 0; k < K_; k++) {
            float bv = FNEGMAX; int bi = 1 << 30;
            #pragma unroll
            for (int q = 0; q < 20; q++) {            // 640 = 20*32
                int j2 = lane + (q << 5);
                float v = sc[wb * 640 + j2];
                if (v > bv || (v == bv && j2 < bi)) { bv = v; bi = j2; }
            }
            #pragma unroll
            for (int off = 16; off > 0; off >>= 1) {
                float ov = __shfl_down_sync(0xffffffffu, bv, off);
                int   oi = __shfl_down_sync(0xffffffffu, bi, off);
                if (ov > bv || (ov == bv && oi < bi)) { bv = ov; bi = oi; }
            }
            bi = __shfl_sync(0xffffffffu, bi, 0);
            bv = __shfl_sync(0xffffffffu, bv, 0);
            if (lane == 0) {
                sc[wb * 640 + bi] = FNEGMAX;
                int gi = base + bi;
                int valid = g_sel_valid[gi];
                float4 bb = g_sel_box[gi];
                float* ob = out + wb * 32 + k * 4;
                if (valid) {
                    ob[0] = fminf(fmaxf(bb.x, 0.f), 1.f);
                    ob[1] = fminf(fmaxf(bb.y, 0.f), 1.f);
                    ob[2] = fminf(fmaxf(bb.z, 0.f), 1.f);
                    ob[3] = fminf(fmaxf(bb.w, 0.f), 1.f);
                    out[B_ * 32 + wb * 8 + k] = bv;
                    out[B_ * 40 + wb * 8 + k] = (float)(bi >> 3);   // class = idx // K
                    vcnt++;
                } else {
                    ob[0] = ob[1] = ob[2] = ob[3] = 0.f;
                    out[B_ * 32 + wb * 8 + k] = 0.f;
                    out[B_ * 40 + wb * 8 + k] = 0.f;
                }
            }
            __syncwarp();
        }
        if (lane == 0) out[B_ * 48 + wb] = (float)vcnt;
    }
    __syncthreads();
    if (tid == 0) g_done_count = 0;      // self-clean for next replay
}

extern "C" void kernel_launch(void* const* d_in, const int* in_sizes, int n_in,
                              void* d_out, int out_size)
{
    const float* boxes  = (const float*)d_in[0];
    const float* scores = (const float*)d_in[1];
    if (n_in >= 2 && in_sizes[0] > in_sizes[1]) {   // defensive input order
        const float* t = boxes; boxes = scores; scores = t;
    }
    dim3 g1(196, B_);                               // 196*1024 >= 200000 float4
    p1_collect<<<g1, 256>>>(scores);
    p2_nms<<<B_ * C_, 128>>>(boxes, scores, (float*)d_out);
}

// round 8
// speedup vs baseline: 1.1256x; 1.1256x over previous
#include <cuda_runtime.h>
#include <cstdint>

#define B_ 8
#define N_ 10000
#define C_ 80
#define K_ 8
#define THR 0.5f
#define T2  0.99f            // collection threshold: ~100 candidates/class
#define FNEGMAX -3.402823466e38f
#define NMS_NEG -1e9f
#define CAP 256
#define NBLK (B_ * C_)       // 640

typedef unsigned long long u64;

// Scratch (allocation-free rule: __device__ globals; zero-initialized; every
// launch restores all counters to zero => graph-replay deterministic)
__device__ u64    g_cand[NBLK * CAP];
__device__ int    g_ccnt[NBLK * 32];      // 128B stride per counter (atomics)
__device__ float  g_sel_score[NBLK * K_];
__device__ float4 g_sel_box  [NBLK * K_];
__device__ int    g_sel_valid[NBLK * K_];
__device__ int    g_barrier[B_];
__device__ int    g_done;

// key = (score_bits, N-n): max-key == (max score, lowest n). Valid scores are
// positive floats (uint order == float order); 0 = empty sentinel.
__device__ __forceinline__ u64 mkey(float v, int n) {
    return (((u64)__float_as_uint(v)) << 32) | (unsigned)(N_ - n);
}

__device__ __forceinline__ bool sup_iou(float4 a, float4 q) {
    float ih = fmaxf(fminf(a.z, q.z) - fmaxf(a.x, q.x), 0.0f);
    float iw = fmaxf(fminf(a.w, q.w) - fmaxf(a.y, q.y), 0.0f);
    float inter = ih * iw;
    float uni = (a.z - a.x) * (a.w - a.y) + (q.z - q.x) * (q.w - q.y) - inter;
    return inter / fmaxf(uni, 1e-9f) > 0.5f;
}

// ---------------------------------------------------------------------------
// ONE kernel. grid=640 blocks x 128 thr (all resident in wave 1: >=8 blk/SM
// fit, so the spin barrier is deadlock-free).
//  Phase A: block i streams slice i%80 (125 rows x 80 classes, 40KB coalesced)
//           of batch i/80; appends keys >T2 to per-class candidate lists.
//  Barrier: per-batch arrive+spin (80 arrivals).
//  Phase B: block i = class (b,c): warp-0 register greedy NMS over <=256 keys
//           (redux-based pops, batched box prefetch, warp-parallel IoU).
//  Ticket:  last block runs fused per-batch top-8 + resets counters.
// Output (f32): boxes[8][8][4] | scores[8][8] | classes[8][8] | valid[8]
// ---------------------------------------------------------------------------
__global__ __launch_bounds__(128) void nms_all(
    const float* __restrict__ boxes, const float* __restrict__ scores,
    float* __restrict__ out)
{
    __shared__ float  topkbuf[B_ * 640];   // 20KB, used only by last block
    __shared__ float4 selbox[K_];
    __shared__ float  selsc[K_];
    __shared__ int    sel_n[K_];
    __shared__ int    sh_nsel, sh_tick, sh_cnt;

    const int tid  = threadIdx.x;
    const int lane = tid & 31;
    const int blk  = blockIdx.x;
    const int b    = blk / C_;
    const int c    = blk % C_;           // doubles as phase-A slice id

    // ================= Phase A: stream slice + collect =================
    {
        const float4* sp = reinterpret_cast<const float4*>(scores)
                         + (size_t)b * 200000 + c * 2500;
        const int cbase = b * C_;
        #pragma unroll
        for (int k = 0; k < 20; k++) {               // 2500 = 19*128 + 68
            int i = tid + (k << 7);
            if (i < 2500) {
                float4 v = __ldg(sp + i);
                int n  = c * 125 + i / 20;           // global box row
                int c0 = (i % 20) * 4;               // class of v.x
                if (v.x > T2) { int p = atomicAdd(&g_ccnt[(cbase+c0  )*32], 1); if (p < CAP) g_cand[(cbase+c0  )*CAP+p] = mkey(v.x, n); }
                if (v.y > T2) { int p = atomicAdd(&g_ccnt[(cbase+c0+1)*32], 1); if (p < CAP) g_cand[(cbase+c0+1)*CAP+p] = mkey(v.y, n); }
                if (v.z > T2) { int p = atomicAdd(&g_ccnt[(cbase+c0+2)*32], 1); if (p < CAP) g_cand[(cbase+c0+2)*CAP+p] = mkey(v.z, n); }
                if (v.w > T2) { int p = atomicAdd(&g_ccnt[(cbase+c0+3)*32], 1); if (p < CAP) g_cand[(cbase+c0+3)*CAP+p] = mkey(v.w, n); }
            }
        }
    }
    __syncthreads();

    // ================= per-batch barrier (all blocks resident) =========
    if (tid == 0) {
        __threadfence();
        atomicAdd(&g_barrier[b], 1);
        volatile int* bp = &g_barrier[b];
        while (*bp < C_) { }
        __threadfence();                  // acquire; CCTL.IVALL cleans L1
        sh_cnt = g_ccnt[blk * 32];
        g_ccnt[blk * 32] = 0;             // self-clean for next replay
    }
    __syncthreads();

    // ================= Phase B: warp-0 register NMS ====================
    const int  cnt = sh_cnt;
    const int  m   = (cnt > CAP) ? 0 : cnt;   // overflow -> exact fallback

    if (tid < 32) {
        const float4* bxp = reinterpret_cast<const float4*>(boxes) + (size_t)b * N_;

        u64 k[8];
        #pragma unroll
        for (int j = 0; j < 8; j++) {
            int idx = lane + (j << 5);
            k[j] = (idx < m) ? __ldg(&g_cand[blk * CAP + idx]) : 0ULL;
        }

        int  nsel = 0;
        bool exhausted = (m == 0);
        while (nsel < K_ && !exhausted) {
            float4 myb = make_float4(0.f, 0.f, 0.f, 0.f);
            float  mysc = 0.f;
            int    myn  = 0;
            int    npop = 0;
            for (int p = 0; p < 8; p++) {
                // lane-local max, then 2x redux (score-hi, then N-n lo)
                u64 g = k[0];
                #pragma unroll
                for (int j = 1; j < 8; j++) if (k[j] > g) g = k[j];
                unsigned hi = (unsigned)(g >> 32);
                unsigned bh = __reduce_max_sync(0xffffffffu, hi);
                if (bh == 0u) { exhausted = true; break; }
                unsigned lo = (hi == bh) ? (unsigned)g : 0u;
                unsigned bl = __reduce_max_sync(0xffffffffu, lo);
                u64 gbest = (((u64)bh) << 32) | bl;
                if (lane == p) {                       // record + prefetch box
                    mysc = __uint_as_float(bh);
                    myn  = N_ - (int)bl;
                    myb  = __ldg(bxp + myn);
                }
                #pragma unroll
                for (int j = 0; j < 8; j++) if (k[j] == gbest) k[j] = 0;  // kill
                npop++;
            }

            for (int q = 0; q < npop && nsel < K_; q++) {
                float4 bb;
                bb.x = __shfl_sync(0xffffffffu, myb.x, q);
                bb.y = __shfl_sync(0xffffffffu, myb.y, q);
                bb.z = __shfl_sync(0xffffffffu, myb.z, q);
                bb.w = __shfl_sync(0xffffffffu, myb.w, q);
                float scq = __shfl_sync(0xffffffffu, mysc, q);
                int   nq  = __shfl_sync(0xffffffffu, myn, q);
                bool sup = (lane < nsel) ? sup_iou(bb, selbox[lane]) : false;
                if (!__ballot_sync(0xffffffffu, sup)) {
                    if (lane == 0) {
                        selbox[nsel] = bb; selsc[nsel] = scq; sel_n[nsel] = nq;
                    }
                    nsel++;
                    __syncwarp();
                }
            }
        }

        // ---- exact fallback (probability ~0 on this data) ----
        if (nsel < K_) {
            const float* scp = scores + (size_t)b * N_ * C_ + c;
            while (nsel < K_) {
                u64 best = 0;
                for (int n = lane; n < N_; n += 32) {
                    float v = __ldg(scp + (size_t)n * C_);
                    if (v > THR) {
                        bool excl = false;
                        for (int j = 0; j < nsel; j++) if (sel_n[j] == n) excl = true;
                        if (!excl) {
                            float4 bb = __ldg(bxp + n);
                            for (int j = 0; j < nsel; j++)
                                if (sup_iou(bb, selbox[j])) { excl = true; break; }
                        }
                        if (!excl) { u64 kk = mkey(v, n); if (kk > best) best = kk; }
                    }
                }
                #pragma unroll
                for (int off = 16; off > 0; off >>= 1) {
                    u64 ob = __shfl_down_sync(0xffffffffu, best, off);
                    if (ob > best) best = ob;
                }
                best = __shfl_sync(0xffffffffu, best, 0);
                if ((unsigned)(best >> 32) == 0u) break;
                int nn = N_ - (int)(best & 0xffffffffu);
                if (lane == 0) {
                    selbox[nsel] = __ldg(bxp + nn);
                    selsc[nsel]  = __uint_as_float((unsigned)(best >> 32));
                    sel_n[nsel]  = nn;
                }
                nsel++;
                __syncwarp();
            }
        }
        if (lane == 0) sh_nsel = nsel;
    }
    __syncthreads();

    if (tid < K_) {
        int o = blk * K_ + tid;
        int v = (tid < sh_nsel);
        g_sel_valid[o] = v;
        g_sel_score[o] = v ? selsc[tid] : NMS_NEG;
        float4 z = make_float4(0.f, 0.f, 0.f, 0.f);
        g_sel_box[o] = v ? selbox[tid] : z;
    }
    __threadfence();
    __syncthreads();
    if (tid == 0) sh_tick = atomicAdd(&g_done, 1);
    __syncthreads();
    if (sh_tick != NBLK - 1) return;
    __threadfence();

    // ================= fused final top-8 (last block): 4 warps x 2 batches ==
    const int warp = tid >> 5;
    for (int wb = warp; wb < B_; wb += 4) {
        const int base = wb * C_ * K_;
        float* sc = topkbuf + wb * 640;
        for (int j2 = lane; j2 < C_ * K_; j2 += 32)
            sc[j2] = g_sel_score[base + j2];
        __syncwarp();

        int vcnt = 0;
        for (int k = 0; k < K_; k++) {
            float bv = FNEGMAX; int bi = 1 << 30;
            #pragma unroll
            for (int q = 0; q < 20; q++) {            // 640 = 20*32
                int j2 = lane + (q << 5);
                float v = sc[j2];
                if (v > bv || (v == bv && j2 < bi)) { bv = v; bi = j2; }
            }
            #pragma unroll
            for (int off = 16; off > 0; off >>= 1) {
                float ov = __shfl_down_sync(0xffffffffu, bv, off);
                int   oi = __shfl_down_sync(0xffffffffu, bi, off);
                if (ov > bv || (ov == bv && oi < bi)) { bv = ov; bi = oi; }
            }
            bi = __shfl_sync(0xffffffffu, bi, 0);
            bv = __shfl_sync(0xffffffffu, bv, 0);
            if (lane == 0) {
                sc[bi] = FNEGMAX;
                int gi = base + bi;
                int valid = g_sel_valid[gi];
                float4 bb = g_sel_box[gi];
                float* ob = out + wb * 32 + k * 4;
                if (valid) {
                    ob[0] = fminf(fmaxf(bb.x, 0.f), 1.f);
                    ob[1] = fminf(fmaxf(bb.y, 0.f), 1.f);
                    ob[2] = fminf(fmaxf(bb.z, 0.f), 1.f);
                    ob[3] = fminf(fmaxf(bb.w, 0.f), 1.f);
                    out[B_ * 32 + wb * 8 + k] = bv;
                    out[B_ * 40 + wb * 8 + k] = (float)(bi >> 3);   // class = idx // K
                    vcnt++;
                } else {
                    ob[0] = ob[1] = ob[2] = ob[3] = 0.f;
                    out[B_ * 32 + wb * 8 + k] = 0.f;
                    out[B_ * 40 + wb * 8 + k] = 0.f;
                }
            }
            __syncwarp();
        }
        if (lane == 0) out[B_ * 48 + wb] = (float)vcnt;
    }
    __syncthreads();
    if (tid == 0) {                       // self-clean for next graph replay
        g_done = 0;
        #pragma unroll
        for (int i = 0; i < B_; i++) g_barrier[i] = 0;
    }
}

extern "C" void kernel_launch(void* const* d_in, const int* in_sizes, int n_in,
                              void* d_out, int out_size)
{
    const float* boxes  = (const float*)d_in[0];
    const float* scores = (const float*)d_in[1];
    if (n_in >= 2 && in_sizes[0] > in_sizes[1]) {   // defensive input order
        const float* t = boxes; boxes = scores; scores = t;
    }
    nms_all<<<NBLK, 128>>>(boxes, scores, (float*)d_out);
}

// round 9
// speedup vs baseline: 1.7253x; 1.5328x over previous
#include <cuda_runtime.h>
#include <cstdint>

#define B_ 8
#define N_ 10000
#define C_ 80
#define K_ 8
#define THR 0.5f
#define T2  0.99f            // collection threshold: ~100 candidates/class
#define NMS_NEG -1e9f
#define CAP 256
#define NBLK (B_ * C_)       // 640

typedef unsigned long long u64;

// Scratch (allocation-free rule: __device__ globals; zero-initialized; every
// launch restores all counters to zero => graph-replay deterministic)
__device__ u64    g_cand[NBLK * CAP];
__device__ int    g_ccnt[NBLK * 32];      // 128B stride per counter (atomics)
__device__ float  g_sel_score[NBLK * K_];
__device__ float4 g_sel_box  [NBLK * K_];
__device__ int    g_barrier[B_];
__device__ int    g_done;

// key = (score_bits, N-n): max-key == (max score, lowest n). Valid scores are
// positive floats (uint order == float order); 0 = empty sentinel.
__device__ __forceinline__ u64 mkey(float v, int n) {
    return (((u64)__float_as_uint(v)) << 32) | (unsigned)(N_ - n);
}

__device__ __forceinline__ bool sup_iou(float4 a, float4 q) {
    float ih = fmaxf(fminf(a.z, q.z) - fmaxf(a.x, q.x), 0.0f);
    float iw = fmaxf(fminf(a.w, q.w) - fmaxf(a.y, q.y), 0.0f);
    float inter = ih * iw;
    float uni = (a.z - a.x) * (a.w - a.y) + (q.z - q.x) * (q.w - q.y) - inter;
    return inter / fmaxf(uni, 1e-9f) > 0.5f;
}

// ---------------------------------------------------------------------------
// ONE kernel, grid 640 x 256 thr. __launch_bounds__(256,5) caps regs at 51 so
// 5 blocks/SM fit (148*5=740 >= 640): ALL blocks wave-1 resident => the spin
// barrier cannot deadlock. smem is tiny (topk is register-based).
//  Phase A: block (b,c) streams rows [125c,125c+125) of batch b (40KB,
//           coalesced, streaming hint); appends keys >T2 per class.
//  Barrier: per-batch arrive+spin (80 arrivals).
//  Phase B: warp 0 register greedy NMS over <=256 keys.
//  Ticket:  last block: register top-8 per batch (warp = batch) + cleanup.
// Output (f32): boxes[8][8][4] | scores[8][8] | classes[8][8] | valid[8]
// ---------------------------------------------------------------------------
__global__ __launch_bounds__(256, 5) void nms_all(
    const float* __restrict__ boxes, const float* __restrict__ scores,
    float* __restrict__ out)
{
    __shared__ float4 selbox[K_];
    __shared__ float  selsc[K_];
    __shared__ int    sel_n[K_];
    __shared__ int    sh_nsel, sh_tick, sh_cnt;

    const int tid  = threadIdx.x;
    const int lane = tid & 31;
    const int blk  = blockIdx.x;
    const int b    = blk / C_;
    const int c    = blk % C_;           // doubles as phase-A slice id

    // ================= Phase A: stream slice + collect =================
    {
        const float4* sp = reinterpret_cast<const float4*>(scores)
                         + (size_t)b * 200000 + c * 2500;
        const int cbase = b * C_;
        #pragma unroll
        for (int k = 0; k < 10; k++) {               // 2500 = 9*256 + 196
            int i = tid + (k << 8);
            if (i < 2500) {
                float4 v = __ldcs(sp + i);           // stream, no reuse
                int n  = c * 125 + i / 20;           // global box row
                int c0 = (i % 20) * 4;               // class of v.x
                if (v.x > T2) { int p = atomicAdd(&g_ccnt[(cbase+c0  )*32], 1); if (p < CAP) g_cand[(cbase+c0  )*CAP+p] = mkey(v.x, n); }
                if (v.y > T2) { int p = atomicAdd(&g_ccnt[(cbase+c0+1)*32], 1); if (p < CAP) g_cand[(cbase+c0+1)*CAP+p] = mkey(v.y, n); }
                if (v.z > T2) { int p = atomicAdd(&g_ccnt[(cbase+c0+2)*32], 1); if (p < CAP) g_cand[(cbase+c0+2)*CAP+p] = mkey(v.z, n); }
                if (v.w > T2) { int p = atomicAdd(&g_ccnt[(cbase+c0+3)*32], 1); if (p < CAP) g_cand[(cbase+c0+3)*CAP+p] = mkey(v.w, n); }
            }
        }
    }
    __syncthreads();

    // ================= per-batch barrier (all blocks resident) =========
    if (tid == 0) {
        __threadfence();
        atomicAdd(&g_barrier[b], 1);
        volatile int* bp = &g_barrier[b];
        while (*bp < C_) { }
        __threadfence();                  // acquire
        sh_cnt = g_ccnt[blk * 32];
        g_ccnt[blk * 32] = 0;             // self-clean for next replay
    }
    __syncthreads();

    // ================= Phase B: warp-0 register NMS ====================
    const int  cnt = sh_cnt;
    const int  m   = (cnt > CAP) ? 0 : cnt;   // overflow -> exact fallback

    if (tid < 32) {
        const float4* bxp = reinterpret_cast<const float4*>(boxes) + (size_t)b * N_;

        u64 k[8];
        #pragma unroll
        for (int j = 0; j < 8; j++) {
            int idx = lane + (j << 5);
            k[j] = (idx < m) ? __ldg(&g_cand[blk * CAP + idx]) : 0ULL;
        }

        int  nsel = 0;
        bool exhausted = (m == 0);
        while (nsel < K_ && !exhausted) {
            float4 myb = make_float4(0.f, 0.f, 0.f, 0.f);
            float  mysc = 0.f;
            int    myn  = 0;
            int    npop = 0;
            for (int p = 0; p < 8; p++) {
                u64 g = k[0];
                #pragma unroll
                for (int j = 1; j < 8; j++) if (k[j] > g) g = k[j];
                unsigned hi = (unsigned)(g >> 32);
                unsigned bh = __reduce_max_sync(0xffffffffu, hi);
                if (bh == 0u) { exhausted = true; break; }
                unsigned lo = (hi == bh) ? (unsigned)g : 0u;
                unsigned bl = __reduce_max_sync(0xffffffffu, lo);
                u64 gbest = (((u64)bh) << 32) | bl;
                if (lane == p) {                       // record + prefetch box
                    mysc = __uint_as_float(bh);
                    myn  = N_ - (int)bl;
                    myb  = __ldg(bxp + myn);
                }
                #pragma unroll
                for (int j = 0; j < 8; j++) if (k[j] == gbest) k[j] = 0;  // kill
                npop++;
            }

            for (int q = 0; q < npop && nsel < K_; q++) {
                float4 bb;
                bb.x = __shfl_sync(0xffffffffu, myb.x, q);
                bb.y = __shfl_sync(0xffffffffu, myb.y, q);
                bb.z = __shfl_sync(0xffffffffu, myb.z, q);
                bb.w = __shfl_sync(0xffffffffu, myb.w, q);
                float scq = __shfl_sync(0xffffffffu, mysc, q);
                int   nq  = __shfl_sync(0xffffffffu, myn, q);
                bool sup = (lane < nsel) ? sup_iou(bb, selbox[lane]) : false;
                if (!__ballot_sync(0xffffffffu, sup)) {
                    if (lane == 0) {
                        selbox[nsel] = bb; selsc[nsel] = scq; sel_n[nsel] = nq;
                    }
                    nsel++;
                    __syncwarp();
                }
            }
        }

        // ---- exact fallback (probability ~0 on this data) ----
        if (nsel < K_) {
            const float* scp = scores + (size_t)b * N_ * C_ + c;
            while (nsel < K_) {
                u64 best = 0;
                for (int n = lane; n < N_; n += 32) {
                    float v = __ldg(scp + (size_t)n * C_);
                    if (v > THR) {
                        bool excl = false;
                        for (int j = 0; j < nsel; j++) if (sel_n[j] == n) excl = true;
                        if (!excl) {
                            float4 bb = __ldg(bxp + n);
                            for (int j = 0; j < nsel; j++)
                                if (sup_iou(bb, selbox[j])) { excl = true; break; }
                        }
                        if (!excl) { u64 kk = mkey(v, n); if (kk > best) best = kk; }
                    }
                }
                #pragma unroll
                for (int off = 16; off > 0; off >>= 1) {
                    u64 ob = __shfl_down_sync(0xffffffffu, best, off);
                    if (ob > best) best = ob;
                }
                best = __shfl_sync(0xffffffffu, best, 0);
                if ((unsigned)(best >> 32) == 0u) break;
                int nn = N_ - (int)(best & 0xffffffffu);
                if (lane == 0) {
                    selbox[nsel] = __ldg(bxp + nn);
                    selsc[nsel]  = __uint_as_float((unsigned)(best >> 32));
                    sel_n[nsel]  = nn;
                }
                nsel++;
                __syncwarp();
            }
        }
        if (lane == 0) sh_nsel = nsel;
    }
    __syncthreads();

    if (tid < K_) {
        int o = blk * K_ + tid;
        int v = (tid < sh_nsel);
        g_sel_score[o] = v ? selsc[tid] : NMS_NEG;   // invalid -> NEG (< THR)
        float4 z = make_float4(0.f, 0.f, 0.f, 0.f);
        g_sel_box[o] = v ? selbox[tid] : z;
    }
    __threadfence();
    __syncthreads();
    if (tid == 0) sh_tick = atomicAdd(&g_done, 1);
    __syncthreads();
    if (sh_tick != NBLK - 1) return;
    __threadfence();

    // ======== fused final top-8 (last block): register-based, warp=batch ====
    {
        const int wb = tid >> 5;              // 8 warps, one batch each
        const int base = wb * C_ * K_;
        // key = (score_bits, 2047-j): max == (max score, lowest flat index j)
        u64 kk[20];
        #pragma unroll
        for (int q = 0; q < 20; q++) {        // j = lane + 32q, coalesced
            int j = lane + (q << 5);
            float v = g_sel_score[base + j];
            kk[q] = (v > THR)
                  ? ((((u64)__float_as_uint(v)) << 32) | (unsigned)(2047 - j))
                  : 0ULL;
        }
        int vcnt = 0;
        for (int k = 0; k < K_; k++) {
            u64 g = kk[0];
            #pragma unroll
            for (int q = 1; q < 20; q++) if (kk[q] > g) g = kk[q];
            unsigned hi = (unsigned)(g >> 32);
            unsigned bh = __reduce_max_sync(0xffffffffu, hi);
            float* ob = out + wb * 32 + k * 4;
            if (bh != 0u) {
                unsigned lo = (hi == bh) ? (unsigned)g : 0u;
                unsigned bl = __reduce_max_sync(0xffffffffu, lo);
                u64 gbest = (((u64)bh) << 32) | bl;
                #pragma unroll
                for (int q = 0; q < 20; q++) if (kk[q] == gbest) kk[q] = 0;
                int j = 2047 - (int)bl;
                if (lane == 0) {
                    float4 bb = g_sel_box[base + j];
                    ob[0] = fminf(fmaxf(bb.x, 0.f), 1.f);
                    ob[1] = fminf(fmaxf(bb.y, 0.f), 1.f);
                    ob[2] = fminf(fmaxf(bb.z, 0.f), 1.f);
                    ob[3] = fminf(fmaxf(bb.w, 0.f), 1.f);
                    out[B_ * 32 + wb * 8 + k] = __uint_as_float(bh);
                    out[B_ * 40 + wb * 8 + k] = (float)(j >> 3);   // class = j // K
                }
                vcnt++;
            } else if (lane == 0) {
                ob[0] = ob[1] = ob[2] = ob[3] = 0.f;
                out[B_ * 32 + wb * 8 + k] = 0.f;
                out[B_ * 40 + wb * 8 + k] = 0.f;
            }
        }
        if (lane == 0) out[B_ * 48 + wb] = (float)vcnt;
    }
    __syncthreads();
    if (tid == 0) {                       // self-clean for next graph replay
        g_done = 0;
        #pragma unroll
        for (int i = 0; i < B_; i++) g_barrier[i] = 0;
    }
}

extern "C" void kernel_launch(void* const* d_in, const int* in_sizes, int n_in,
                              void* d_out, int out_size)
{
    const float* boxes  = (const float*)d_in[0];
    const float* scores = (const float*)d_in[1];
    if (n_in >= 2 && in_sizes[0] > in_sizes[1]) {   // defensive input order
        const float* t = boxes; boxes = scores; scores = t;
    }
    nms_all<<<NBLK, 256>>>(boxes, scores, (float*)d_out);
}